// round 15
// baseline (speedup 1.0000x reference)
#include <cuda_runtime.h>

#define NN 100000
#define EE 1600000
#define FULLMASK 0xffffffffu

// Scratch (static __device__ arrays per harness rules)
__device__ int   g_cnt[NN];      // zero-init at load; self-cleaned by k_scan each run
__device__ int   g_rowptr[NN + 1];
__device__ int   g_cursor[NN];
__device__ int   g_col[EE];
__device__ unsigned long long g_tile[256];   // lookback scan: (state<<32)|sum; zeroed by k_count
__device__ float g_dinv[NN];
__device__ float g_xd[NN];
__device__ float g_p1[NN * 64];  // node d, lane l -> float2 {f_l, f_{l+32}} at ((float2*)g_p1)[d*32+l]

__global__ void k_count(const int* __restrict__ ei) {
    int t = blockIdx.x * blockDim.x + threadIdx.x;
    if (blockIdx.x == 0 && threadIdx.x < 256) g_tile[threadIdx.x] = 0ULL;  // reset lookback table
    if (t < EE / 4) {
        int4 d4 = ((const int4*)(ei + EE))[t];
        atomicAdd(&g_cnt[d4.x], 1);
        atomicAdd(&g_cnt[d4.y], 1);
        atomicAdd(&g_cnt[d4.z], 1);
        atomicAdd(&g_cnt[d4.w], 1);
    }
}

// Single-pass decoupled-lookback exclusive scan over g_cnt.
// 196 blocks x 512 threads; also produces cursor, dinv, xd; self-cleans g_cnt.
__global__ void __launch_bounds__(512) k_scan(const float* __restrict__ x) {
    __shared__ int ws[16];
    __shared__ int s_prefix;
    int b = blockIdx.x, tid = threadIdx.x;
    int lane = tid & 31, wid = tid >> 5;
    int i = b * 512 + tid;
    int v = (i < NN) ? g_cnt[i] : 0;
    if (i < NN) g_cnt[i] = 0;          // self-clean for next graph replay

    int xc = v;
    for (int d = 1; d < 32; d <<= 1) {
        int n = __shfl_up_sync(FULLMASK, xc, d);
        if (lane >= d) xc += n;
    }
    if (lane == 31) ws[wid] = xc;
    __syncthreads();
    if (wid == 0) {
        int w = (lane < 16) ? ws[lane] : 0;
        for (int d = 1; d < 16; d <<= 1) {
            int n = __shfl_up_sync(FULLMASK, w, d);
            if (lane >= d) w += n;
        }
        if (lane < 16) ws[lane] = w;
    }
    __syncthreads();
    int excl_local = ((wid > 0) ? ws[wid - 1] : 0) + xc - v;
    int total = ws[15];

    if (tid == 0) {
        if (b == 0) {
            atomicExch(&g_tile[0], (2ULL << 32) | (unsigned)total);
            s_prefix = 0;
        } else {
            atomicExch(&g_tile[b], (1ULL << 32) | (unsigned)total);
            int pref = 0, j = b - 1;
            while (1) {
                unsigned long long t;
                do {
                    t = *((volatile unsigned long long*)&g_tile[j]);
                } while ((t >> 32) == 0ULL);
                pref += (int)(unsigned)t;
                if ((t >> 32) == 2ULL) break;
                j--;
            }
            atomicExch(&g_tile[b], (2ULL << 32) | (unsigned)(pref + total));
            s_prefix = pref;
        }
    }
    __syncthreads();
    int excl = s_prefix + excl_local;
    if (i < NN) {
        g_rowptr[i] = excl;
        g_cursor[i] = excl;
        float dv = rsqrtf((float)(v + 1));   // deg includes self-loop
        g_dinv[i] = dv;
        g_xd[i]   = x[i] * dv;
    }
    if (b == 0 && tid == 0) g_rowptr[NN] = EE;
}

__global__ void k_fill(const int* __restrict__ ei) {
    int t = blockIdx.x * blockDim.x + threadIdx.x;
    if (t < EE / 4) {
        int4 s4 = ((const int4*)ei)[t];
        int4 d4 = ((const int4*)(ei + EE))[t];
        int p0 = atomicAdd(&g_cursor[d4.x], 1);
        int p1 = atomicAdd(&g_cursor[d4.y], 1);
        int p2 = atomicAdd(&g_cursor[d4.z], 1);
        int p3 = atomicAdd(&g_cursor[d4.w], 1);
        g_col[p0] = s4.x;
        g_col[p1] = s4.y;
        g_col[p2] = s4.z;
        g_col[p3] = s4.w;
    }
}

__device__ __forceinline__ float silu_f(float v) {
    return v / (1.0f + __expf(-v));
}

__device__ __forceinline__ unsigned long long pack2(float a, float b) {
    unsigned long long r;
    asm("mov.b64 %0, {%1, %2};" : "=l"(r) : "f"(a), "f"(b));
    return r;
}
__device__ __forceinline__ unsigned long long fma2(unsigned long long a,
                                                   unsigned long long b,
                                                   unsigned long long c) {
    unsigned long long d;
    asm("fma.rn.f32x2 %0, %1, %2, %3;" : "=l"(d) : "l"(a), "l"(b), "l"(c));
    return d;
}
__device__ __forceinline__ float2 unpack2(unsigned long long v) {
    float2 f;
    asm("mov.b64 {%0, %1}, %2;" : "=f"(f.x), "=f"(f.y) : "l"(v));
    return f;
}

// Layer 1: phase 1 = TWO threads per node (row split at midpoint) for 2x
// aggregation parallelism; phase 2 = warp-per-node expansion from smem.
__global__ void __launch_bounds__(256) k_l1(const float* __restrict__ W1,
                                            const float* __restrict__ b1) {
    __shared__ float s_part[256];
    __shared__ float s_a1[128];
    int tid = threadIdx.x;
    int nloc = tid & 127, half = tid >> 7;
    int n = blockIdx.x * 128 + nloc;

    float s = 0.f;
    if (n < NN) {
        int j0 = g_rowptr[n], j1 = g_rowptr[n + 1];
        int mid = (j0 + j1) >> 1;
        int a = half ? mid : j0;
        int b = half ? j1 : mid;
        float s0 = 0.f, s1 = 0.f;
        int j = a;
        for (; j + 2 <= b; j += 2) {
            s0 += g_xd[g_col[j]];
            s1 += g_xd[g_col[j + 1]];
        }
        for (; j < b; j++) s0 += g_xd[g_col[j]];
        s = s0 + s1;
    }
    s_part[tid] = s;
    __syncthreads();
    if (tid < 128) {
        int nn = blockIdx.x * 128 + tid;
        if (nn < NN) {
            float tot = s_part[tid] + s_part[tid + 128];
            s_a1[tid] = (tot + g_xd[nn]) * g_dinv[nn];   // self-loop term: xd[nn]
        }
    }
    __syncthreads();

    // Phase 2: warp w expands 16 contiguous nodes
    int lane = tid & 31, w = tid >> 5;
    float w1lo = W1[lane], w1hi = W1[lane + 32];
    float blo = b1[lane],  bhi = b1[lane + 32];
    int base = blockIdx.x * 128 + (w << 4);
#pragma unroll 4
    for (int it = 0; it < 16; it++) {
        int d = base + it;
        if (d >= NN) break;
        float a  = s_a1[(w << 4) + it];
        float dv = g_dinv[d];                 // uniform across warp -> 1 L2 request
        float h0 = silu_f(fmaf(a, w1lo, blo));
        float h1 = silu_f(fmaf(a, w1hi, bhi));
        ((float2*)g_p1)[(d << 5) + lane] = make_float2(h0 * dv, h1 * dv);
    }
}

// Fused layer-2 aggregation + MLP head. Warp handles 4 nodes.
// Aggregation processes the 4 rows' chunks INTERLEAVED: up to 16 independent
// row-gathers in flight per iteration (vs 4 when rows are walked serially).
// MLP: k-split f32x2 GEMVs with smem-broadcast activations.
__global__ void __launch_bounds__(256) k_l2mlp(
    const float* __restrict__ W2, const float* __restrict__ b2,
    const float* __restrict__ W3, const float* __restrict__ b3,
    const float* __restrict__ W4, const float* __restrict__ b4,
    float* __restrict__ out)
{
    __shared__ unsigned long long sW2kp[32][64];
    __shared__ unsigned long long sW3kp[32][64];
    __shared__ unsigned long long tsm[8][4][32];
    int tid = threadIdx.x;
    for (int idx = tid; idx < 32 * 64; idx += 256) {
        int k = idx >> 6, j = idx & 63;
        sW2kp[k][j] = pack2(W2[k * 64 + j], W2[(k + 32) * 64 + j]);
        sW3kp[k][j] = pack2(W3[k * 64 + j], W3[(k + 32) * 64 + j]);
    }
    __syncthreads();

    int lane = tid & 31, w = tid >> 5;
    float b2lo = b2[lane], b2hi = b2[lane + 32];
    float b3lo = b3[lane], b3hi = b3[lane + 32];
    float w4lo = W4[lane], w4hi = W4[lane + 32];
    float b4v = b4[0];

    const float2* __restrict__ p = (const float2*)g_p1;
    int wg = (blockIdx.x * 256 + tid) >> 5;
    int wT = (gridDim.x * 256) >> 5;

    for (int g = wg; g < NN / 4; g += wT) {
        int d0 = g << 2;
        // Batch-load all 5 row pointers (d0 % 4 == 0 -> 16B aligned)
        int4 rp4 = *reinterpret_cast<const int4*>(&g_rowptr[d0]);
        int rp5 = g_rowptr[d0 + 4];
        int rb[5] = {rp4.x, rp4.y, rp4.z, rp4.w, rp5};
        int len0 = rb[1] - rb[0], len1 = rb[2] - rb[1];
        int len2 = rb[3] - rb[2], len3 = rb[4] - rb[3];
        int mx = max(max(len0, len1), max(len2, len3));

        float2 acc[4];
#pragma unroll
        for (int m = 0; m < 4; m++)
            acc[m] = p[((d0 + m) << 5) + lane];   // self-loop term p1[d]

        // ---- Interleaved chunked aggregation: chunk k of all 4 rows ----
        for (int k = 0; k + 4 <= mx; k += 4) {
#pragma unroll
            for (int m = 0; m < 4; m++) {
                int j = rb[m] + k;
                if (j + 4 <= rb[m + 1]) {
                    int c0 = g_col[j], c1 = g_col[j + 1];
                    int c2 = g_col[j + 2], c3 = g_col[j + 3];
                    float2 v0 = p[(c0 << 5) + lane];
                    float2 v1 = p[(c1 << 5) + lane];
                    float2 v2 = p[(c2 << 5) + lane];
                    float2 v3 = p[(c3 << 5) + lane];
                    acc[m].x += (v0.x + v1.x) + (v2.x + v3.x);
                    acc[m].y += (v0.y + v1.y) + (v2.y + v3.y);
                }
            }
        }
        // ---- Tails (< 4 edges per row) ----
#pragma unroll
        for (int m = 0; m < 4; m++) {
            int lenm = rb[m + 1] - rb[m];
            for (int j = rb[m] + (lenm & ~3); j < rb[m + 1]; j++) {
                float2 v = p[(g_col[j] << 5) + lane];
                acc[m].x += v.x;
                acc[m].y += v.y;
            }
        }

        __syncwarp();   // previous iteration's GEMV2 reads of tsm are done
#pragma unroll
        for (int m = 0; m < 4; m++) {
            float dv = g_dinv[d0 + m];
            tsm[w][m][lane] = pack2(acc[m].x * dv, acc[m].y * dv);
        }
        __syncwarp();

        // ---- GEMV 1: t @ W2 + b2 (k-split) ----
        unsigned long long accA[4], accB[4];
#pragma unroll
        for (int m = 0; m < 4; m++) {
            accA[m] = pack2(b2lo, 0.f);
            accB[m] = pack2(b2hi, 0.f);
        }
#pragma unroll
        for (int k = 0; k < 32; k++) {
            unsigned long long wA = sW2kp[k][lane];
            unsigned long long wB = sW2kp[k][lane + 32];
#pragma unroll
            for (int m = 0; m < 4; m++) {
                unsigned long long tv = tsm[w][m][k];
                accA[m] = fma2(tv, wA, accA[m]);
                accB[m] = fma2(tv, wB, accB[m]);
            }
        }
        __syncwarp();
        {
#pragma unroll
            for (int m = 0; m < 4; m++) {
                float2 a = unpack2(accA[m]);
                float2 bq = unpack2(accB[m]);
                float hlo = silu_f(a.x + a.y);
                float hhi = silu_f(bq.x + bq.y);
                tsm[w][m][lane] = pack2(hlo, hhi);
            }
        }
        __syncwarp();

        // ---- GEMV 2: h @ W3 + b3 (k-split) ----
#pragma unroll
        for (int m = 0; m < 4; m++) {
            accA[m] = pack2(b3lo, 0.f);
            accB[m] = pack2(b3hi, 0.f);
        }
#pragma unroll
        for (int k = 0; k < 32; k++) {
            unsigned long long wA = sW3kp[k][lane];
            unsigned long long wB = sW3kp[k][lane + 32];
#pragma unroll
            for (int m = 0; m < 4; m++) {
                unsigned long long tv = tsm[w][m][k];
                accA[m] = fma2(tv, wA, accA[m]);
                accB[m] = fma2(tv, wB, accB[m]);
            }
        }

        // ---- Output: silu + dot with W4 ----
#pragma unroll
        for (int m = 0; m < 4; m++) {
            float2 a = unpack2(accA[m]);
            float2 bq = unpack2(accB[m]);
            float hlo = silu_f(a.x + a.y);
            float hhi = silu_f(bq.x + bq.y);
            float part = hlo * w4lo + hhi * w4hi;
            for (int o = 16; o; o >>= 1) part += __shfl_xor_sync(FULLMASK, part, o);
            if (lane == 0) out[d0 + m] = part + b4v;
        }
    }
}

extern "C" void kernel_launch(void* const* d_in, const int* in_sizes, int n_in,
                              void* d_out, int out_size) {
    const float* x  = (const float*)d_in[0];
    const int*   ei = (const int*)d_in[1];
    const float* W1 = (const float*)d_in[2];
    const float* b1 = (const float*)d_in[3];
    const float* W2 = (const float*)d_in[4];
    const float* b2 = (const float*)d_in[5];
    const float* W3 = (const float*)d_in[6];
    const float* b3 = (const float*)d_in[7];
    const float* W4 = (const float*)d_in[8];
    const float* b4 = (const float*)d_in[9];
    float* out = (float*)d_out;

    k_count<<<(EE / 4 + 255) / 256, 256>>>(ei);
    k_scan <<<196, 512>>>(x);
    k_fill <<<(EE / 4 + 255) / 256, 256>>>(ei);
    k_l1   <<<(NN + 127) / 128, 256>>>(W1, b1);
    k_l2mlp<<<888, 256>>>(W2, b2, W3, b3, W4, b4, out);
}

// round 17
// speedup vs baseline: 1.0724x; 1.0724x over previous
#include <cuda_runtime.h>

#define NN 100000
#define EE 1600000
#define FULLMASK 0xffffffffu

// Scratch (static __device__ arrays per harness rules)
__device__ int   g_cnt[NN];      // zero-init at load; self-cleaned by k_scan each run
__device__ int   g_rowptr[NN + 1];
__device__ unsigned char g_slot[EE];   // per-edge slot within dst row (from k_count's atomic)
__device__ int   g_col[EE];
__device__ unsigned long long g_tile[256];   // lookback scan: (state<<32)|sum; zeroed by k_count
__device__ float g_dinv[NN];
__device__ float g_xd[NN];
__device__ float g_p1[NN * 64];  // node d, lane l -> float2 {f_l, f_{l+32}} at ((float2*)g_p1)[d*32+l]

// Count pass: atomicAdd's return value IS the edge's slot within its dst row.
__global__ void k_count(const int* __restrict__ ei) {
    int t = blockIdx.x * blockDim.x + threadIdx.x;
    if (blockIdx.x == 0 && threadIdx.x < 256) g_tile[threadIdx.x] = 0ULL;  // reset lookback table
    if (t < EE / 4) {
        int4 d4 = ((const int4*)(ei + EE))[t];
        uchar4 s;
        s.x = (unsigned char)atomicAdd(&g_cnt[d4.x], 1);
        s.y = (unsigned char)atomicAdd(&g_cnt[d4.y], 1);
        s.z = (unsigned char)atomicAdd(&g_cnt[d4.z], 1);
        s.w = (unsigned char)atomicAdd(&g_cnt[d4.w], 1);
        ((uchar4*)g_slot)[t] = s;
    }
}

// Single-pass decoupled-lookback exclusive scan over g_cnt.
// 196 blocks x 512 threads; also produces dinv, xd; self-cleans g_cnt.
__global__ void __launch_bounds__(512) k_scan(const float* __restrict__ x) {
    __shared__ int ws[16];
    __shared__ int s_prefix;
    int b = blockIdx.x, tid = threadIdx.x;
    int lane = tid & 31, wid = tid >> 5;
    int i = b * 512 + tid;
    int v = (i < NN) ? g_cnt[i] : 0;
    if (i < NN) g_cnt[i] = 0;          // self-clean for next graph replay

    int xc = v;
    for (int d = 1; d < 32; d <<= 1) {
        int n = __shfl_up_sync(FULLMASK, xc, d);
        if (lane >= d) xc += n;
    }
    if (lane == 31) ws[wid] = xc;
    __syncthreads();
    if (wid == 0) {
        int w = (lane < 16) ? ws[lane] : 0;
        for (int d = 1; d < 16; d <<= 1) {
            int n = __shfl_up_sync(FULLMASK, w, d);
            if (lane >= d) w += n;
        }
        if (lane < 16) ws[lane] = w;
    }
    __syncthreads();
    int excl_local = ((wid > 0) ? ws[wid - 1] : 0) + xc - v;
    int total = ws[15];

    if (tid == 0) {
        if (b == 0) {
            atomicExch(&g_tile[0], (2ULL << 32) | (unsigned)total);
            s_prefix = 0;
        } else {
            atomicExch(&g_tile[b], (1ULL << 32) | (unsigned)total);
            int pref = 0, j = b - 1;
            while (1) {
                unsigned long long t;
                do {
                    t = *((volatile unsigned long long*)&g_tile[j]);
                } while ((t >> 32) == 0ULL);
                pref += (int)(unsigned)t;
                if ((t >> 32) == 2ULL) break;
                j--;
            }
            atomicExch(&g_tile[b], (2ULL << 32) | (unsigned)(pref + total));
            s_prefix = pref;
        }
    }
    __syncthreads();
    int excl = s_prefix + excl_local;
    if (i < NN) {
        g_rowptr[i] = excl;
        float dv = rsqrtf((float)(v + 1));   // deg includes self-loop
        g_dinv[i] = dv;
        g_xd[i]   = x[i] * dv;
    }
    if (b == 0 && tid == 0) g_rowptr[NN] = EE;
}

// Atomic-free fill: p = rowptr[dst] + slot (slot recorded by k_count).
__global__ void k_fill(const int* __restrict__ ei) {
    int t = blockIdx.x * blockDim.x + threadIdx.x;
    if (t < EE / 4) {
        int4 s4 = ((const int4*)ei)[t];
        int4 d4 = ((const int4*)(ei + EE))[t];
        uchar4 sl = ((const uchar4*)g_slot)[t];
        g_col[g_rowptr[d4.x] + sl.x] = s4.x;
        g_col[g_rowptr[d4.y] + sl.y] = s4.y;
        g_col[g_rowptr[d4.z] + sl.z] = s4.z;
        g_col[g_rowptr[d4.w] + sl.w] = s4.w;
    }
}

__device__ __forceinline__ float silu_f(float v) {
    return v / (1.0f + __expf(-v));
}

__device__ __forceinline__ unsigned long long pack2(float a, float b) {
    unsigned long long r;
    asm("mov.b64 %0, {%1, %2};" : "=l"(r) : "f"(a), "f"(b));
    return r;
}
__device__ __forceinline__ unsigned long long fma2(unsigned long long a,
                                                   unsigned long long b,
                                                   unsigned long long c) {
    unsigned long long d;
    asm("fma.rn.f32x2 %0, %1, %2, %3;" : "=l"(d) : "l"(a), "l"(b), "l"(c));
    return d;
}
__device__ __forceinline__ float2 unpack2(unsigned long long v) {
    float2 f;
    asm("mov.b64 {%0, %1}, %2;" : "=f"(f.x), "=f"(f.y) : "l"(v));
    return f;
}

// Layer 1: phase 1 = TWO threads per node (row split at midpoint) for 2x
// aggregation parallelism; phase 2 = warp-per-node expansion from smem.
__global__ void __launch_bounds__(256) k_l1(const float* __restrict__ W1,
                                            const float* __restrict__ b1) {
    __shared__ float s_part[256];
    __shared__ float s_a1[128];
    int tid = threadIdx.x;
    int nloc = tid & 127, half = tid >> 7;
    int n = blockIdx.x * 128 + nloc;

    float s = 0.f;
    if (n < NN) {
        int j0 = g_rowptr[n], j1 = g_rowptr[n + 1];
        int mid = (j0 + j1) >> 1;
        int a = half ? mid : j0;
        int b = half ? j1 : mid;
        float s0 = 0.f, s1 = 0.f;
        int j = a;
        for (; j + 2 <= b; j += 2) {
            s0 += g_xd[g_col[j]];
            s1 += g_xd[g_col[j + 1]];
        }
        for (; j < b; j++) s0 += g_xd[g_col[j]];
        s = s0 + s1;
    }
    s_part[tid] = s;
    __syncthreads();
    if (tid < 128) {
        int nn = blockIdx.x * 128 + tid;
        if (nn < NN) {
            float tot = s_part[tid] + s_part[tid + 128];
            s_a1[tid] = (tot + g_xd[nn]) * g_dinv[nn];   // self-loop term: xd[nn]
        }
    }
    __syncthreads();

    // Phase 2: warp w expands 16 contiguous nodes
    int lane = tid & 31, w = tid >> 5;
    float w1lo = W1[lane], w1hi = W1[lane + 32];
    float blo = b1[lane],  bhi = b1[lane + 32];
    int base = blockIdx.x * 128 + (w << 4);
#pragma unroll 4
    for (int it = 0; it < 16; it++) {
        int d = base + it;
        if (d >= NN) break;
        float a  = s_a1[(w << 4) + it];
        float dv = g_dinv[d];                 // uniform across warp -> 1 L2 request
        float h0 = silu_f(fmaf(a, w1lo, blo));
        float h1 = silu_f(fmaf(a, w1hi, bhi));
        ((float2*)g_p1)[(d << 5) + lane] = make_float2(h0 * dv, h1 * dv);
    }
}

// Fused layer-2 aggregation + MLP head. Warp handles 4 nodes (proven best shape,
// R11 serial-row gather). MLP: k-split f32x2 GEMVs, smem-broadcast activations.
__global__ void __launch_bounds__(256) k_l2mlp(
    const float* __restrict__ W2, const float* __restrict__ b2,
    const float* __restrict__ W3, const float* __restrict__ b3,
    const float* __restrict__ W4, const float* __restrict__ b4,
    float* __restrict__ out)
{
    __shared__ unsigned long long sW2kp[32][64];
    __shared__ unsigned long long sW3kp[32][64];
    __shared__ unsigned long long tsm[8][4][32];
    int tid = threadIdx.x;
    for (int idx = tid; idx < 32 * 64; idx += 256) {
        int k = idx >> 6, j = idx & 63;
        sW2kp[k][j] = pack2(W2[k * 64 + j], W2[(k + 32) * 64 + j]);
        sW3kp[k][j] = pack2(W3[k * 64 + j], W3[(k + 32) * 64 + j]);
    }
    __syncthreads();

    int lane = tid & 31, w = tid >> 5;
    float b2lo = b2[lane], b2hi = b2[lane + 32];
    float b3lo = b3[lane], b3hi = b3[lane + 32];
    float w4lo = W4[lane], w4hi = W4[lane + 32];
    float b4v = b4[0];

    const float2* __restrict__ p = (const float2*)g_p1;
    int wg = (blockIdx.x * 256 + tid) >> 5;
    int wT = (gridDim.x * 256) >> 5;

    for (int g = wg; g < NN / 4; g += wT) {
        int d0 = g << 2;
        // Batch-load all 5 row pointers (d0 % 4 == 0 -> 16B aligned)
        int4 rp4 = *reinterpret_cast<const int4*>(&g_rowptr[d0]);
        int rp5 = g_rowptr[d0 + 4];
        int rb[5] = {rp4.x, rp4.y, rp4.z, rp4.w, rp5};
        __syncwarp();   // previous iteration's GEMV2 reads of tsm are done

        // ---- Aggregation: 4 CSR rows -> tsm[w][m][lane] = {a_l, a_l+32} ----
#pragma unroll
        for (int m = 0; m < 4; m++) {
            int d = d0 + m;
            float2 acc = p[(d << 5) + lane];   // self-loop term p1[d]
            int j = rb[m], e = rb[m + 1];
            for (; j + 4 <= e; j += 4) {
                int c0 = g_col[j], c1 = g_col[j + 1], c2 = g_col[j + 2], c3 = g_col[j + 3];
                float2 v0 = p[(c0 << 5) + lane];
                float2 v1 = p[(c1 << 5) + lane];
                float2 v2 = p[(c2 << 5) + lane];
                float2 v3 = p[(c3 << 5) + lane];
                acc.x += (v0.x + v1.x) + (v2.x + v3.x);
                acc.y += (v0.y + v1.y) + (v2.y + v3.y);
            }
            for (; j < e; j++) {
                float2 v = p[(g_col[j] << 5) + lane];
                acc.x += v.x;
                acc.y += v.y;
            }
            float dv = g_dinv[d];
            tsm[w][m][lane] = pack2(acc.x * dv, acc.y * dv);
        }
        __syncwarp();

        // ---- GEMV 1: t @ W2 + b2 (k-split) ----
        unsigned long long accA[4], accB[4];
#pragma unroll
        for (int m = 0; m < 4; m++) {
            accA[m] = pack2(b2lo, 0.f);
            accB[m] = pack2(b2hi, 0.f);
        }
#pragma unroll
        for (int k = 0; k < 32; k++) {
            unsigned long long wA = sW2kp[k][lane];
            unsigned long long wB = sW2kp[k][lane + 32];
#pragma unroll
            for (int m = 0; m < 4; m++) {
                unsigned long long tv = tsm[w][m][k];
                accA[m] = fma2(tv, wA, accA[m]);
                accB[m] = fma2(tv, wB, accB[m]);
            }
        }
        __syncwarp();
        {
#pragma unroll
            for (int m = 0; m < 4; m++) {
                float2 a = unpack2(accA[m]);
                float2 bq = unpack2(accB[m]);
                float hlo = silu_f(a.x + a.y);
                float hhi = silu_f(bq.x + bq.y);
                tsm[w][m][lane] = pack2(hlo, hhi);
            }
        }
        __syncwarp();

        // ---- GEMV 2: h @ W3 + b3 (k-split) ----
#pragma unroll
        for (int m = 0; m < 4; m++) {
            accA[m] = pack2(b3lo, 0.f);
            accB[m] = pack2(b3hi, 0.f);
        }
#pragma unroll
        for (int k = 0; k < 32; k++) {
            unsigned long long wA = sW3kp[k][lane];
            unsigned long long wB = sW3kp[k][lane + 32];
#pragma unroll
            for (int m = 0; m < 4; m++) {
                unsigned long long tv = tsm[w][m][k];
                accA[m] = fma2(tv, wA, accA[m]);
                accB[m] = fma2(tv, wB, accB[m]);
            }
        }

        // ---- Output: silu + dot with W4 ----
#pragma unroll
        for (int m = 0; m < 4; m++) {
            float2 a = unpack2(accA[m]);
            float2 bq = unpack2(accB[m]);
            float hlo = silu_f(a.x + a.y);
            float hhi = silu_f(bq.x + bq.y);
            float part = hlo * w4lo + hhi * w4hi;
            for (int o = 16; o; o >>= 1) part += __shfl_xor_sync(FULLMASK, part, o);
            if (lane == 0) out[d0 + m] = part + b4v;
        }
    }
}

extern "C" void kernel_launch(void* const* d_in, const int* in_sizes, int n_in,
                              void* d_out, int out_size) {
    const float* x  = (const float*)d_in[0];
    const int*   ei = (const int*)d_in[1];
    const float* W1 = (const float*)d_in[2];
    const float* b1 = (const float*)d_in[3];
    const float* W2 = (const float*)d_in[4];
    const float* b2 = (const float*)d_in[5];
    const float* W3 = (const float*)d_in[6];
    const float* b3 = (const float*)d_in[7];
    const float* W4 = (const float*)d_in[8];
    const float* b4 = (const float*)d_in[9];
    float* out = (float*)d_out;

    k_count<<<(EE / 4 + 255) / 256, 256>>>(ei);
    k_scan <<<196, 512>>>(x);
    k_fill <<<(EE / 4 + 255) / 256, 256>>>(ei);
    k_l1   <<<(NN + 127) / 128, 256>>>(W1, b1);
    k_l2mlp<<<888, 256>>>(W2, b2, W3, b3, W4, b4, out);
}